// round 3
// baseline (speedup 1.0000x reference)
#include <cuda_runtime.h>
#include <math_constants.h>

// Problem constants
#define TT   128          // sequence length
#define BB   8            // batch
#define DD   512          // embed dim
#define HH   8            // heads
#define HD   64           // head dim
#define II   64           // B*H
#define SCALING 0.125f    // 64^-0.5
// LAMBDA = 1.0 (folded)

// ---------------- scratch (no allocations allowed) ----------------
__device__ float g_q[II * TT * HD];     // [i][t][hd], scaled
__device__ float g_k[II * TT * HD];
__device__ float g_v[II * TT * HD];
__device__ float g_attn[TT * BB * DD];  // row m = a*8+b, col = h*64+d

// =================================================================
// Kernel 1: packed in-projection.  C[m][n] = A[m][:]·W[n][:] + b[n]
// grid (8, 16, 3): x = N tiles (512/64), y = M tiles (1024/64), z = q/k/v
// 256 threads, 4x4 per thread, 64x64x16 tiles.
// Scatters outputs to per-head layout g_{q,k,v}[i][row][t].
// =================================================================
__global__ __launch_bounds__(256) void proj_kernel(
    const float* __restrict__ qin, const float* __restrict__ kin,
    const float* __restrict__ vin, const float* __restrict__ W,
    const float* __restrict__ bias)
{
    __shared__ float As[16 * 68];
    __shared__ float Bs[16 * 68];

    const int z = blockIdx.z;
    const float* A  = (z == 0) ? qin : ((z == 1) ? kin : vin);
    const float* Wz = W + z * DD * DD;
    const float* bz = bias + z * DD;
    float* dst      = (z == 0) ? g_q : ((z == 1) ? g_k : g_v);

    const int m0 = blockIdx.y * 64;
    const int n0 = blockIdx.x * 64;
    const int tid = threadIdx.x;
    const int tm0 = (tid >> 4) << 2;
    const int tn0 = (tid & 15) << 2;

    float acc[4][4];
#pragma unroll
    for (int r = 0; r < 4; r++)
#pragma unroll
        for (int c = 0; c < 4; c++) acc[r][c] = 0.f;

    for (int k0 = 0; k0 < DD; k0 += 16) {
        for (int idx = tid; idx < 1024; idx += 256) {
            const int row = idx >> 4, kk = idx & 15;
            As[kk * 68 + row] = A[(m0 + row) * DD + k0 + kk];
            Bs[kk * 68 + row] = Wz[(n0 + row) * DD + k0 + kk];
        }
        __syncthreads();
#pragma unroll
        for (int kk = 0; kk < 16; kk++) {
            const float4 av = *(const float4*)(As + kk * 68 + tm0);
            const float4 bv = *(const float4*)(Bs + kk * 68 + tn0);
            const float a[4] = {av.x, av.y, av.z, av.w};
            const float b[4] = {bv.x, bv.y, bv.z, bv.w};
#pragma unroll
            for (int r = 0; r < 4; r++)
#pragma unroll
                for (int c = 0; c < 4; c++)
                    acc[r][c] = fmaf(a[r], b[c], acc[r][c]);
        }
        __syncthreads();
    }

    const float scale = (z == 0) ? SCALING : 1.0f;
#pragma unroll
    for (int r = 0; r < 4; r++) {
#pragma unroll
        for (int c = 0; c < 4; c++) {
            const int m = m0 + tm0 + r;          // = a*8 + b
            const int n = n0 + tn0 + c;          // = h*64 + t
            const float val = (acc[r][c] + bz[n]) * scale;
            const int a_ = m >> 3, b_ = m & 7;
            const int h_ = n >> 6, t_ = n & 63;
            const int i_ = b_ * HH + h_;
            dst[(i_ * TT + a_) * HD + t_] = val;
        }
    }
}

// =================================================================
// Kernel 2: cube + fuse + softmax + attn@q.
// grid (128, 8): x = query row a, y = batch b.  256 threads.
// Per block: bias tile [128][128] resident; loop 8 heads:
//   S[kb,c] = sum_t K[kb,t] * (q_a[t]*V[c,t]);  fused = mean_c + max_c (S+bias)
//   softmax over kb; attn row = sum_kb w[kb]*q[kb,:]
// =================================================================
#define KT_STRIDE 132
#define SM_FLOATS (16384 + 8448 + 8448 + 64 + 128 + 128 + 16)
#define SM_BYTES  (SM_FLOATS * 4)

__global__ __launch_bounds__(256) void cube_kernel(const float* __restrict__ bias_g)
{
    extern __shared__ float sm[];
    float* biasS  = sm;               // 128*128
    float* Kt     = biasS + 16384;    // [t][kb]  64 x 132
    float* Vt     = Kt + 8448;        // [t][c]   64 x 132 (pre-scaled by q_a[t])
    float* qaS    = Vt + 8448;        // 64
    float* fusedS = qaS + 64;         // 128
    float* wS     = fusedS + 128;     // 128
    float* red    = wS + 128;         // 16

    const int aq = blockIdx.x, b = blockIdx.y;
    const int tid  = threadIdx.x;
    const int lane = tid & 31, wid = tid >> 5;
    const int cg = tid & 15;
    const int r0 = (tid >> 4) << 3;
    const int c0 = cg << 3;

    // bias tile for (b, aq): read once from HBM, coalesced
    const float* bsrc = bias_g + ((b * TT + aq) * TT) * TT;
    for (int idx = tid; idx < TT * TT; idx += 256) biasS[idx] = bsrc[idx];

    for (int h = 0; h < HH; ++h) {
        const int i = b * HH + h;

        if (tid < 64) qaS[tid] = g_q[(i * TT + aq) * HD + tid];
        __syncthreads();

        // build transposed K / (q_a-scaled) V tiles
        for (int idx = tid; idx < TT * HD; idx += 256) {
            const int c = idx >> 6, t = idx & 63;
            const float kv = g_k[(i * TT + c) * HD + t];
            const float vv = g_v[(i * TT + c) * HD + t];
            Kt[t * KT_STRIDE + c] = kv;
            Vt[t * KT_STRIDE + c] = qaS[t] * vv;
        }
        __syncthreads();

        // main trilinear tile: 8x8 per thread, 64 k-steps
        float acc[8][8];
#pragma unroll
        for (int r = 0; r < 8; r++)
#pragma unroll
            for (int c = 0; c < 8; c++) acc[r][c] = 0.f;

#pragma unroll 2
        for (int t = 0; t < HD; t++) {
            const float* kr = Kt + t * KT_STRIDE;
            const float* vr = Vt + t * KT_STRIDE;
            const float4 w0 = *(const float4*)(kr + r0);
            const float4 w1 = *(const float4*)(kr + r0 + 4);
            const float4 v0 = *(const float4*)(vr + c0);
            const float4 v1 = *(const float4*)(vr + c0 + 4);
            const float w[8] = {w0.x, w0.y, w0.z, w0.w, w1.x, w1.y, w1.z, w1.w};
            const float v[8] = {v0.x, v0.y, v0.z, v0.w, v1.x, v1.y, v1.z, v1.w};
#pragma unroll
            for (int r = 0; r < 8; r++)
#pragma unroll
                for (int c = 0; c < 8; c++)
                    acc[r][c] = fmaf(w[r], v[c], acc[r][c]);
        }

        // add bias, reduce over c (mean + max), combine across the 16 col-groups
#pragma unroll
        for (int r = 0; r < 8; r++) {
            const float* bro = biasS + (r0 + r) * TT + c0;
            float mx = -CUDART_INF_F, sum = 0.f;
#pragma unroll
            for (int c = 0; c < 8; c++) {
                const float s = acc[r][c] + bro[c];  // LAMBDA = 1
                sum += s;
                mx = fmaxf(mx, s);
            }
#pragma unroll
            for (int o = 8; o >= 1; o >>= 1) {
                sum += __shfl_xor_sync(0xffffffffu, sum, o);
                mx = fmaxf(mx, __shfl_xor_sync(0xffffffffu, mx, o));
            }
            if (cg == 0) fusedS[r0 + r] = sum * (1.0f / 128.0f) + mx;
        }
        __syncthreads();

        // softmax over kb (128 values)
        const float x = (tid < TT) ? fusedS[tid] : -CUDART_INF_F;
        float m_ = x;
#pragma unroll
        for (int o = 16; o >= 1; o >>= 1)
            m_ = fmaxf(m_, __shfl_xor_sync(0xffffffffu, m_, o));
        if (lane == 0) red[wid] = m_;
        __syncthreads();
        if (tid == 0) {
            float mm = red[0];
            for (int w = 1; w < 8; w++) mm = fmaxf(mm, red[w]);
            red[8] = mm;
        }
        __syncthreads();
        const float bm = red[8];
        const float e = (tid < TT) ? __expf(x - bm) : 0.f;
        if (tid < TT) wS[tid] = e;
        float s_ = e;
#pragma unroll
        for (int o = 16; o >= 1; o >>= 1)
            s_ += __shfl_xor_sync(0xffffffffu, s_, o);
        if (lane == 0) red[wid] = s_;
        __syncthreads();
        if (tid == 0) {
            float ss = 0.f;
            for (int w = 0; w < 8; w++) ss += red[w];
            red[8] = ss;
        }
        __syncthreads();
        const float inv = 1.0f / red[8];

        // attn row: sum_kb w[kb] * q[i][kb][d]   (coalesced over d)
        if (tid < HD) {
            const float* qi = g_q + i * TT * HD + tid;
            float a0 = 0.f, a1 = 0.f, a2 = 0.f, a3 = 0.f;
#pragma unroll 4
            for (int kb = 0; kb < TT; kb += 4) {
                a0 = fmaf(wS[kb + 0], qi[(kb + 0) * HD], a0);
                a1 = fmaf(wS[kb + 1], qi[(kb + 1) * HD], a1);
                a2 = fmaf(wS[kb + 2], qi[(kb + 2) * HD], a2);
                a3 = fmaf(wS[kb + 3], qi[(kb + 3) * HD], a3);
            }
            g_attn[(aq * BB + b) * DD + h * HD + tid] = ((a0 + a1) + (a2 + a3)) * inv;
        }
        __syncthreads();
    }
}

// =================================================================
// Kernel 3: out projection. out[m][n] = g_attn[m][:]·out_w[n][:] + out_b[n]
// grid (8, 16), 256 threads, same tiling as proj.
// =================================================================
__global__ __launch_bounds__(256) void outproj_kernel(
    const float* __restrict__ Wo, const float* __restrict__ bo,
    float* __restrict__ out)
{
    __shared__ float As[16 * 68];
    __shared__ float Bs[16 * 68];

    const int m0 = blockIdx.y * 64;
    const int n0 = blockIdx.x * 64;
    const int tid = threadIdx.x;
    const int tm0 = (tid >> 4) << 2;
    const int tn0 = (tid & 15) << 2;

    float acc[4][4];
#pragma unroll
    for (int r = 0; r < 4; r++)
#pragma unroll
        for (int c = 0; c < 4; c++) acc[r][c] = 0.f;

    for (int k0 = 0; k0 < DD; k0 += 16) {
        for (int idx = tid; idx < 1024; idx += 256) {
            const int row = idx >> 4, kk = idx & 15;
            As[kk * 68 + row] = g_attn[(m0 + row) * DD + k0 + kk];
            Bs[kk * 68 + row] = Wo[(n0 + row) * DD + k0 + kk];
        }
        __syncthreads();
#pragma unroll
        for (int kk = 0; kk < 16; kk++) {
            const float4 av = *(const float4*)(As + kk * 68 + tm0);
            const float4 bv = *(const float4*)(Bs + kk * 68 + tn0);
            const float a[4] = {av.x, av.y, av.z, av.w};
            const float b[4] = {bv.x, bv.y, bv.z, bv.w};
#pragma unroll
            for (int r = 0; r < 4; r++)
#pragma unroll
                for (int c = 0; c < 4; c++)
                    acc[r][c] = fmaf(a[r], b[c], acc[r][c]);
        }
        __syncthreads();
    }

#pragma unroll
    for (int r = 0; r < 4; r++)
#pragma unroll
        for (int c = 0; c < 4; c++) {
            const int m = m0 + tm0 + r;
            const int n = n0 + tn0 + c;
            out[m * DD + n] = acc[r][c] + bo[n];
        }
}

// =================================================================
extern "C" void kernel_launch(void* const* d_in, const int* in_sizes, int n_in,
                              void* d_out, int out_size)
{
    (void)in_sizes; (void)n_in; (void)out_size;
    const float* q   = (const float*)d_in[0];
    const float* k   = (const float*)d_in[1];
    const float* v   = (const float*)d_in[2];
    const float* cb  = (const float*)d_in[3];
    const float* ipw = (const float*)d_in[4];
    const float* ipb = (const float*)d_in[5];
    const float* ow  = (const float*)d_in[6];
    const float* ob  = (const float*)d_in[7];
    float* out = (float*)d_out;

    cudaFuncSetAttribute(cube_kernel,
                         cudaFuncAttributeMaxDynamicSharedMemorySize, SM_BYTES);

    proj_kernel<<<dim3(8, 16, 3), 256>>>(q, k, v, ipw, ipb);
    cube_kernel<<<dim3(128, 8), 256, SM_BYTES>>>(cb);
    outproj_kernel<<<dim3(8, 16), 256>>>(ow, ob, out);
}

// round 7
// speedup vs baseline: 1.0075x; 1.0075x over previous
#include <cuda_runtime.h>
#include <math_constants.h>

// Problem constants
#define TT   128          // sequence length
#define BB   8            // batch
#define DD   512          // embed dim
#define HH   8            // heads
#define HD   64           // head dim
#define II   64           // B*H
#define SCALING 0.125f    // 64^-0.5
// LAMBDA = 1.0 (folded)

typedef unsigned long long u64;

// packed f32x2 helpers (Blackwell FFMA2 path)
__device__ __forceinline__ u64 pack_dup(float w) {
    u64 p;
    unsigned int wu = __float_as_uint(w);
    asm("mov.b64 %0, {%1, %1};" : "=l"(p) : "r"(wu));
    return p;
}
__device__ __forceinline__ void ffma2(u64& d, u64 a, u64 b) {
    asm("fma.rn.f32x2 %0, %1, %2, %0;" : "+l"(d) : "l"(a), "l"(b));
}
__device__ __forceinline__ void unpack2(u64 p, float& lo, float& hi) {
    unsigned int l, h;
    asm("mov.b64 {%0, %1}, %2;" : "=r"(l), "=r"(h) : "l"(p));
    lo = __uint_as_float(l);
    hi = __uint_as_float(h);
}

// ---------------- scratch (no allocations allowed) ----------------
__device__ float g_q[II * TT * HD];     // [i][t][hd], scaled
__device__ float g_k[II * TT * HD];
__device__ float g_v[II * TT * HD];
__device__ float g_attn[TT * BB * DD];  // row m = a*8+b, col = h*64+d

// =================================================================
// Kernel 1: packed in-projection.  C[m][n] = A[m][:]·W[n][:] + b[n]
// grid (8, 16, 3), 256 threads, 4x4 per thread (FFMA2: 4x2 packed).
// =================================================================
__global__ __launch_bounds__(256) void proj_kernel(
    const float* __restrict__ qin, const float* __restrict__ kin,
    const float* __restrict__ vin, const float* __restrict__ W,
    const float* __restrict__ bias)
{
    __shared__ float As[16 * 68];
    __shared__ float Bs[16 * 68];

    const int z = blockIdx.z;
    const float* A  = (z == 0) ? qin : ((z == 1) ? kin : vin);
    const float* Wz = W + z * DD * DD;
    const float* bz = bias + z * DD;
    float* dst      = (z == 0) ? g_q : ((z == 1) ? g_k : g_v);

    const int m0 = blockIdx.y * 64;
    const int n0 = blockIdx.x * 64;
    const int tid = threadIdx.x;
    const int tm0 = (tid >> 4) << 2;
    const int tn0 = (tid & 15) << 2;

    u64 acc2[4][2];
#pragma unroll
    for (int r = 0; r < 4; r++)
#pragma unroll
        for (int c = 0; c < 2; c++) acc2[r][c] = 0ull;

    for (int k0 = 0; k0 < DD; k0 += 16) {
        for (int idx = tid; idx < 1024; idx += 256) {
            const int row = idx >> 4, kk = idx & 15;
            As[kk * 68 + row] = A[(m0 + row) * DD + k0 + kk];
            Bs[kk * 68 + row] = Wz[(n0 + row) * DD + k0 + kk];
        }
        __syncthreads();
#pragma unroll
        for (int kk = 0; kk < 16; kk++) {
            const float4 av = *(const float4*)(As + kk * 68 + tm0);
            const ulonglong2 bv = *(const ulonglong2*)(Bs + kk * 68 + tn0);
            const u64 b2[2] = {bv.x, bv.y};
            const u64 ap[4] = {pack_dup(av.x), pack_dup(av.y),
                               pack_dup(av.z), pack_dup(av.w)};
#pragma unroll
            for (int r = 0; r < 4; r++)
#pragma unroll
                for (int c = 0; c < 2; c++)
                    ffma2(acc2[r][c], ap[r], b2[c]);
        }
        __syncthreads();
    }

    const float scale = (z == 0) ? SCALING : 1.0f;
#pragma unroll
    for (int r = 0; r < 4; r++) {
        float accr[4];
        unpack2(acc2[r][0], accr[0], accr[1]);
        unpack2(acc2[r][1], accr[2], accr[3]);
#pragma unroll
        for (int c = 0; c < 4; c++) {
            const int m = m0 + tm0 + r;          // = a*8 + b
            const int n = n0 + tn0 + c;          // = h*64 + t
            const float val = (accr[c] + bz[n]) * scale;
            const int a_ = m >> 3, b_ = m & 7;
            const int h_ = n >> 6, t_ = n & 63;
            const int i_ = b_ * HH + h_;
            dst[(i_ * TT + a_) * HD + t_] = val;
        }
    }
}

// =================================================================
// Kernel 2: cube + fuse + softmax + attn@q.
// grid (128, 8): x = query row a, y = batch b.  256 threads.
// FFMA2 inner loop: 8 rows x 4 col-pairs packed per thread.
// =================================================================
#define KT_STRIDE 132
#define SM_FLOATS (16384 + 8448 + 8448 + 64 + 128 + 128 + 16)
#define SM_BYTES  (SM_FLOATS * 4)

__global__ __launch_bounds__(256) void cube_kernel(const float* __restrict__ bias_g)
{
    extern __shared__ float sm[];
    float* biasS  = sm;               // 128*128
    float* Kt     = biasS + 16384;    // [t][kb]  64 x 132
    float* Vt     = Kt + 8448;        // [t][c]   64 x 132 (pre-scaled by q_a[t])
    float* qaS    = Vt + 8448;        // 64
    float* fusedS = qaS + 64;         // 128
    float* wS     = fusedS + 128;     // 128
    float* red    = wS + 128;         // 16

    const int aq = blockIdx.x, b = blockIdx.y;
    const int tid  = threadIdx.x;
    const int lane = tid & 31, wid = tid >> 5;
    const int cg = tid & 15;
    const int r0 = (tid >> 4) << 3;
    const int c0 = cg << 3;

    // bias tile for (b, aq): read once from HBM, coalesced
    const float* bsrc = bias_g + ((b * TT + aq) * TT) * TT;
    for (int idx = tid; idx < TT * TT; idx += 256) biasS[idx] = bsrc[idx];

    for (int h = 0; h < HH; ++h) {
        const int i = b * HH + h;

        if (tid < 64) qaS[tid] = g_q[(i * TT + aq) * HD + tid];
        __syncthreads();

        // build transposed K / (q_a-scaled) V tiles
        for (int idx = tid; idx < TT * HD; idx += 256) {
            const int c = idx >> 6, t = idx & 63;
            const float kv = g_k[(i * TT + c) * HD + t];
            const float vv = g_v[(i * TT + c) * HD + t];
            Kt[t * KT_STRIDE + c] = kv;
            Vt[t * KT_STRIDE + c] = qaS[t] * vv;
        }
        __syncthreads();

        // main trilinear tile: 8x8 per thread via FFMA2 (8x4 packed), 64 k-steps
        u64 acc2[8][4];
#pragma unroll
        for (int r = 0; r < 8; r++)
#pragma unroll
            for (int c = 0; c < 4; c++) acc2[r][c] = 0ull;

#pragma unroll 2
        for (int t = 0; t < HD; t++) {
            const float* kr = Kt + t * KT_STRIDE;
            const float* vr = Vt + t * KT_STRIDE;
            const float4 w0 = *(const float4*)(kr + r0);
            const float4 w1 = *(const float4*)(kr + r0 + 4);
            const ulonglong2 va = *(const ulonglong2*)(vr + c0);
            const ulonglong2 vb = *(const ulonglong2*)(vr + c0 + 4);
            const u64 v2[4] = {va.x, va.y, vb.x, vb.y};
            const u64 wp[8] = {pack_dup(w0.x), pack_dup(w0.y),
                               pack_dup(w0.z), pack_dup(w0.w),
                               pack_dup(w1.x), pack_dup(w1.y),
                               pack_dup(w1.z), pack_dup(w1.w)};
#pragma unroll
            for (int r = 0; r < 8; r++)
#pragma unroll
                for (int c = 0; c < 4; c++)
                    ffma2(acc2[r][c], wp[r], v2[c]);
        }

        // add bias, reduce over c (mean + max), combine across the 16 col-groups
#pragma unroll
        for (int r = 0; r < 8; r++) {
            const float* bro = biasS + (r0 + r) * TT + c0;
            float mx = -CUDART_INF_F, sum = 0.f;
#pragma unroll
            for (int c = 0; c < 4; c++) {
                float s0, s1;
                unpack2(acc2[r][c], s0, s1);
                s0 += bro[2 * c];       // LAMBDA = 1
                s1 += bro[2 * c + 1];
                sum += s0 + s1;
                mx = fmaxf(mx, fmaxf(s0, s1));
            }
#pragma unroll
            for (int o = 8; o >= 1; o >>= 1) {
                sum += __shfl_xor_sync(0xffffffffu, sum, o);
                mx = fmaxf(mx, __shfl_xor_sync(0xffffffffu, mx, o));
            }
            if (cg == 0) fusedS[r0 + r] = sum * (1.0f / 128.0f) + mx;
        }
        __syncthreads();

        // softmax over kb (128 values)
        const float x = (tid < TT) ? fusedS[tid] : -CUDART_INF_F;
        float m_ = x;
#pragma unroll
        for (int o = 16; o >= 1; o >>= 1)
            m_ = fmaxf(m_, __shfl_xor_sync(0xffffffffu, m_, o));
        if (lane == 0) red[wid] = m_;
        __syncthreads();
        if (tid == 0) {
            float mm = red[0];
            for (int w = 1; w < 8; w++) mm = fmaxf(mm, red[w]);
            red[8] = mm;
        }
        __syncthreads();
        const float bm = red[8];
        const float e = (tid < TT) ? __expf(x - bm) : 0.f;
        if (tid < TT) wS[tid] = e;
        float s_ = e;
#pragma unroll
        for (int o = 16; o >= 1; o >>= 1)
            s_ += __shfl_xor_sync(0xffffffffu, s_, o);
        if (lane == 0) red[wid] = s_;
        __syncthreads();
        if (tid == 0) {
            float ss = 0.f;
            for (int w = 0; w < 8; w++) ss += red[w];
            red[8] = ss;
        }
        __syncthreads();
        const float inv = 1.0f / red[8];

        // attn row: sum_kb w[kb] * q[i][kb][d]   (coalesced over d)
        if (tid < HD) {
            const float* qi = g_q + i * TT * HD + tid;
            float a0 = 0.f, a1 = 0.f, a2 = 0.f, a3 = 0.f;
#pragma unroll 4
            for (int kb = 0; kb < TT; kb += 4) {
                a0 = fmaf(wS[kb + 0], qi[(kb + 0) * HD], a0);
                a1 = fmaf(wS[kb + 1], qi[(kb + 1) * HD], a1);
                a2 = fmaf(wS[kb + 2], qi[(kb + 2) * HD], a2);
                a3 = fmaf(wS[kb + 3], qi[(kb + 3) * HD], a3);
            }
            g_attn[(aq * BB + b) * DD + h * HD + tid] = ((a0 + a1) + (a2 + a3)) * inv;
        }
        __syncthreads();
    }
}

// =================================================================
// Kernel 3: out projection (FFMA2, same tiling as proj).
// =================================================================
__global__ __launch_bounds__(256) void outproj_kernel(
    const float* __restrict__ Wo, const float* __restrict__ bo,
    float* __restrict__ out)
{
    __shared__ float As[16 * 68];
    __shared__ float Bs[16 * 68];

    const int m0 = blockIdx.y * 64;
    const int n0 = blockIdx.x * 64;
    const int tid = threadIdx.x;
    const int tm0 = (tid >> 4) << 2;
    const int tn0 = (tid & 15) << 2;

    u64 acc2[4][2];
#pragma unroll
    for (int r = 0; r < 4; r++)
#pragma unroll
        for (int c = 0; c < 2; c++) acc2[r][c] = 0ull;

    for (int k0 = 0; k0 < DD; k0 += 16) {
        for (int idx = tid; idx < 1024; idx += 256) {
            const int row = idx >> 4, kk = idx & 15;
            As[kk * 68 + row] = g_attn[(m0 + row) * DD + k0 + kk];
            Bs[kk * 68 + row] = Wo[(n0 + row) * DD + k0 + kk];
        }
        __syncthreads();
#pragma unroll
        for (int kk = 0; kk < 16; kk++) {
            const float4 av = *(const float4*)(As + kk * 68 + tm0);
            const ulonglong2 bv = *(const ulonglong2*)(Bs + kk * 68 + tn0);
            const u64 b2[2] = {bv.x, bv.y};
            const u64 ap[4] = {pack_dup(av.x), pack_dup(av.y),
                               pack_dup(av.z), pack_dup(av.w)};
#pragma unroll
            for (int r = 0; r < 4; r++)
#pragma unroll
                for (int c = 0; c < 2; c++)
                    ffma2(acc2[r][c], ap[r], b2[c]);
        }
        __syncthreads();
    }

#pragma unroll
    for (int r = 0; r < 4; r++) {
        float accr[4];
        unpack2(acc2[r][0], accr[0], accr[1]);
        unpack2(acc2[r][1], accr[2], accr[3]);
#pragma unroll
        for (int c = 0; c < 4; c++) {
            const int m = m0 + tm0 + r;
            const int n = n0 + tn0 + c;
            out[m * DD + n] = accr[c] + bo[n];
        }
    }
}

// =================================================================
extern "C" void kernel_launch(void* const* d_in, const int* in_sizes, int n_in,
                              void* d_out, int out_size)
{
    (void)in_sizes; (void)n_in; (void)out_size;
    const float* q   = (const float*)d_in[0];
    const float* k   = (const float*)d_in[1];
    const float* v   = (const float*)d_in[2];
    const float* cb  = (const float*)d_in[3];
    const float* ipw = (const float*)d_in[4];
    const float* ipb = (const float*)d_in[5];
    const float* ow  = (const float*)d_in[6];
    const float* ob  = (const float*)d_in[7];
    float* out = (float*)d_out;

    cudaFuncSetAttribute(cube_kernel,
                         cudaFuncAttributeMaxDynamicSharedMemorySize, SM_BYTES);

    proj_kernel<<<dim3(8, 16, 3), 256>>>(q, k, v, ipw, ipb);
    cube_kernel<<<dim3(128, 8), 256, SM_BYTES>>>(cb);
    outproj_kernel<<<dim3(8, 16), 256>>>(ow, ob, out);
}

// round 10
// speedup vs baseline: 1.3072x; 1.2975x over previous
#include <cuda_runtime.h>
#include <cuda_bf16.h>
#include <math_constants.h>
#include <cstdint>

// Problem constants
#define TT   128          // sequence length
#define BB   8            // batch
#define DD   512          // embed dim
#define HH   8            // heads
#define HD   64           // head dim
#define II   64           // B*H
#define SCALING 0.125f    // 64^-0.5

typedef unsigned long long u64;

// ---------------- packed f32x2 helpers (proj kernels) ----------------
__device__ __forceinline__ u64 pack_dup(float w) {
    u64 p; unsigned int wu = __float_as_uint(w);
    asm("mov.b64 %0, {%1, %1};" : "=l"(p) : "r"(wu));
    return p;
}
__device__ __forceinline__ void ffma2(u64& d, u64 a, u64 b) {
    asm("fma.rn.f32x2 %0, %1, %2, %0;" : "+l"(d) : "l"(a), "l"(b));
}
__device__ __forceinline__ void unpack2(u64 p, float& lo, float& hi) {
    unsigned int l, h;
    asm("mov.b64 {%0, %1}, %2;" : "=r"(l), "=r"(h) : "l"(p));
    lo = __uint_as_float(l); hi = __uint_as_float(h);
}

// ---------------- warp-MMA helpers (sm_80+ path, valid on sm_103) ----------------
__device__ __forceinline__ uint32_t smem_u32(const void* p) {
    uint32_t a;
    asm("{ .reg .u64 t; cvta.to.shared.u64 t, %1; cvt.u32.u64 %0, t; }" : "=r"(a) : "l"(p));
    return a;
}
__device__ __forceinline__ void ldsm_x4(uint32_t a[4], uint32_t addr) {
    asm volatile("ldmatrix.sync.aligned.m8n8.x4.shared.b16 {%0,%1,%2,%3}, [%4];"
        : "=r"(a[0]), "=r"(a[1]), "=r"(a[2]), "=r"(a[3]) : "r"(addr));
}
__device__ __forceinline__ void ldsm_x2(uint32_t b[2], uint32_t addr) {
    asm volatile("ldmatrix.sync.aligned.m8n8.x2.shared.b16 {%0,%1}, [%2];"
        : "=r"(b[0]), "=r"(b[1]) : "r"(addr));
}
__device__ __forceinline__ void mma16816(float d[4], const uint32_t a[4], const uint32_t b[2]) {
    asm volatile("mma.sync.aligned.m16n8k16.row.col.f32.bf16.bf16.f32 "
        "{%0,%1,%2,%3}, {%4,%5,%6,%7}, {%8,%9}, {%0,%1,%2,%3};"
        : "+f"(d[0]), "+f"(d[1]), "+f"(d[2]), "+f"(d[3])
        : "r"(a[0]), "r"(a[1]), "r"(a[2]), "r"(a[3]), "r"(b[0]), "r"(b[1]));
}
#define SWZ(o) ((o) ^ ((((uint32_t)(o)) >> 3) & 0x70))

// ---------------- scratch (no allocations allowed) ----------------
__device__ float g_q[II * TT * HD];     // [i][t][hd], scaled
__device__ float g_k[II * TT * HD];
__device__ float g_v[II * TT * HD];
__device__ float g_attn[TT * BB * DD];  // row m = a*8+b, col = h*64+d

// =================================================================
// Kernel 1: packed in-projection (unchanged; proven at 75us).
// =================================================================
__global__ __launch_bounds__(256) void proj_kernel(
    const float* __restrict__ qin, const float* __restrict__ kin,
    const float* __restrict__ vin, const float* __restrict__ W,
    const float* __restrict__ bias)
{
    __shared__ float As[16 * 68];
    __shared__ float Bs[16 * 68];

    const int z = blockIdx.z;
    const float* A  = (z == 0) ? qin : ((z == 1) ? kin : vin);
    const float* Wz = W + z * DD * DD;
    const float* bz = bias + z * DD;
    float* dst      = (z == 0) ? g_q : ((z == 1) ? g_k : g_v);

    const int m0 = blockIdx.y * 64;
    const int n0 = blockIdx.x * 64;
    const int tid = threadIdx.x;
    const int tm0 = (tid >> 4) << 2;
    const int tn0 = (tid & 15) << 2;

    u64 acc2[4][2];
#pragma unroll
    for (int r = 0; r < 4; r++)
#pragma unroll
        for (int c = 0; c < 2; c++) acc2[r][c] = 0ull;

    for (int k0 = 0; k0 < DD; k0 += 16) {
        for (int idx = tid; idx < 1024; idx += 256) {
            const int row = idx >> 4, kk = idx & 15;
            As[kk * 68 + row] = A[(m0 + row) * DD + k0 + kk];
            Bs[kk * 68 + row] = Wz[(n0 + row) * DD + k0 + kk];
        }
        __syncthreads();
#pragma unroll
        for (int kk = 0; kk < 16; kk++) {
            const float4 av = *(const float4*)(As + kk * 68 + tm0);
            const ulonglong2 bv = *(const ulonglong2*)(Bs + kk * 68 + tn0);
            const u64 b2[2] = {bv.x, bv.y};
            const u64 ap[4] = {pack_dup(av.x), pack_dup(av.y),
                               pack_dup(av.z), pack_dup(av.w)};
#pragma unroll
            for (int r = 0; r < 4; r++)
#pragma unroll
                for (int c = 0; c < 2; c++)
                    ffma2(acc2[r][c], ap[r], b2[c]);
        }
        __syncthreads();
    }

    const float scale = (z == 0) ? SCALING : 1.0f;
#pragma unroll
    for (int r = 0; r < 4; r++) {
        float accr[4];
        unpack2(acc2[r][0], accr[0], accr[1]);
        unpack2(acc2[r][1], accr[2], accr[3]);
#pragma unroll
        for (int c = 0; c < 4; c++) {
            const int m = m0 + tm0 + r;          // = a*8 + b
            const int n = n0 + tn0 + c;          // = h*64 + t
            const float val = (accr[c] + bz[n]) * scale;
            const int a_ = m >> 3, b_ = m & 7;
            const int h_ = n >> 6, t_ = n & 63;
            const int i_ = b_ * HH + h_;
            dst[(i_ * TT + a_) * HD + t_] = val;
        }
    }
}

// =================================================================
// Kernel 2: cube via warp-level bf16 MMA (split-bf16, 3 MMA terms).
// grid (128, 8): x = aq, y = batch.  256 threads (8 warps).
// Warp w owns S rows [w*16, w*16+16) x all 128 cols.
// =================================================================
// SMEM byte layout: 4 bf16 tiles (128x64, K-major SW128) then float region
#define OFF_KHI  0
#define OFF_KLO  16384
#define OFF_VHI  32768
#define OFF_VLO  49152
#define OFF_FLT  65536
// float-region indices:
#define FI_BIAS  0                    // 128*129 (stride 129)
#define FI_QA    16512                // 64
#define FI_FUSED (16512 + 64)         // 128
#define FI_W     (FI_FUSED + 128)     // 128
#define FI_RED   (FI_W + 128)         // 16
#define SM_FLOATS (FI_RED + 16)
#define SM_BYTES  (OFF_FLT + SM_FLOATS * 4)

__global__ __launch_bounds__(256) void cube_kernel(const float* __restrict__ bias_g)
{
    extern __shared__ char smem[];
    float* fs     = (float*)(smem + OFF_FLT);
    float* biasS  = fs + FI_BIAS;
    float* qaS    = fs + FI_QA;
    float* fusedS = fs + FI_FUSED;
    float* wS     = fs + FI_W;
    float* red    = fs + FI_RED;

    const uint32_t sbase = smem_u32(smem);

    const int aq = blockIdx.x, b = blockIdx.y;
    const int tid  = threadIdx.x;
    const int lane = tid & 31, wid = tid >> 5;
    const int g    = lane >> 2, tig = lane & 3;
    const int m0   = wid * 16;

    // bias tile for (b, aq): [kb][c], padded stride 129
    const float* bsrc = bias_g + ((size_t)(b * TT + aq) * TT) * TT;
    for (int idx = tid; idx < TT * TT; idx += 256) {
        const int kb = idx >> 7, c = idx & 127;
        biasS[kb * 129 + c] = bsrc[idx];
    }

    // ldmatrix source addresses (per-lane, head-invariant)
    // A (K tile): 16x16 frag at (m0, kc*16): row = m0+(lane&15), kbyte = kc*32 + (lane>>4)*16
    // B (V tile): 8x16 frag at (nt*8, kc*16): row = lane&7 (+nt*8), kbyte = kc*32 + ((lane>>3)&1)*16
    uint32_t aoff[4], boff[4];
#pragma unroll
    for (int kc = 0; kc < 4; kc++) {
        aoff[kc] = SWZ((uint32_t)((m0 + (lane & 15)) * 128 + kc * 32 + ((lane >> 4) << 4)));
        boff[kc] = SWZ((uint32_t)((lane & 7) * 128 + kc * 32 + (((lane >> 3) & 1) << 4)));
    }

    for (int h = 0; h < HH; ++h) {
        const int i = b * HH + h;

        if (tid < 64) qaS[tid] = g_q[(i * TT + aq) * HD + tid];
        __syncthreads();

        // convert K and q_a-scaled V into split-bf16 SW128 tiles
        for (int idx = tid; idx < TT * HD; idx += 256) {
            const int r = idx >> 6, t = idx & 63;
            const float kf = g_k[(i * TT + r) * HD + t];
            const float vf = g_v[(i * TT + r) * HD + t] * qaS[t];
            const __nv_bfloat16 kh = __float2bfloat16(kf);
            const __nv_bfloat16 kl = __float2bfloat16(kf - __bfloat162float(kh));
            const __nv_bfloat16 vh = __float2bfloat16(vf);
            const __nv_bfloat16 vl = __float2bfloat16(vf - __bfloat162float(vh));
            const uint32_t off = SWZ((uint32_t)(r * 128 + t * 2));
            *(__nv_bfloat16*)(smem + OFF_KHI + off) = kh;
            *(__nv_bfloat16*)(smem + OFF_KLO + off) = kl;
            *(__nv_bfloat16*)(smem + OFF_VHI + off) = vh;
            *(__nv_bfloat16*)(smem + OFF_VLO + off) = vl;
        }
        __syncthreads();

        // S strip [16 x 128] in registers: acc[nt][4]
        float acc[16][4];
#pragma unroll
        for (int nt = 0; nt < 16; nt++)
#pragma unroll
            for (int j = 0; j < 4; j++) acc[nt][j] = 0.f;

#pragma unroll
        for (int kc = 0; kc < 4; kc++) {
            uint32_t ah[4], al[4];
            ldsm_x4(ah, sbase + OFF_KHI + aoff[kc]);
            ldsm_x4(al, sbase + OFF_KLO + aoff[kc]);
            const uint32_t bo = boff[kc];
#pragma unroll
            for (int nt = 0; nt < 16; nt++) {
                uint32_t bh[2];
                ldsm_x2(bh, sbase + OFF_VHI + bo + nt * 1024);
                mma16816(acc[nt], ah, bh);
                mma16816(acc[nt], al, bh);
            }
#pragma unroll
            for (int nt = 0; nt < 16; nt++) {
                uint32_t bl[2];
                ldsm_x2(bl, sbase + OFF_VLO + bo + nt * 1024);
                mma16816(acc[nt], ah, bl);
            }
        }

        // epilogue: bias add + mean/max over c for rows r0 = m0+g, r1 = r0+8
        {
            const int r0 = m0 + g, r1 = r0 + 8;
            float s0 = 0.f, s1 = 0.f;
            float mx0 = -CUDART_INF_F, mx1 = -CUDART_INF_F;
            const float* b0 = biasS + r0 * 129 + tig * 2;
            const float* b1 = biasS + r1 * 129 + tig * 2;
#pragma unroll
            for (int nt = 0; nt < 16; nt++) {
                const float v00 = acc[nt][0] + b0[nt * 8];
                const float v01 = acc[nt][1] + b0[nt * 8 + 1];
                const float v10 = acc[nt][2] + b1[nt * 8];
                const float v11 = acc[nt][3] + b1[nt * 8 + 1];
                s0 += v00 + v01;  mx0 = fmaxf(mx0, fmaxf(v00, v01));
                s1 += v10 + v11;  mx1 = fmaxf(mx1, fmaxf(v10, v11));
            }
#pragma unroll
            for (int o = 1; o <= 2; o <<= 1) {
                s0  += __shfl_xor_sync(0xffffffffu, s0, o);
                s1  += __shfl_xor_sync(0xffffffffu, s1, o);
                mx0 = fmaxf(mx0, __shfl_xor_sync(0xffffffffu, mx0, o));
                mx1 = fmaxf(mx1, __shfl_xor_sync(0xffffffffu, mx1, o));
            }
            if (tig == 0) {
                fusedS[r0] = s0 * (1.0f / 128.0f) + mx0;
                fusedS[r1] = s1 * (1.0f / 128.0f) + mx1;
            }
        }
        __syncthreads();

        // softmax over kb (128 values)
        const float x = (tid < TT) ? fusedS[tid] : -CUDART_INF_F;
        float m_ = x;
#pragma unroll
        for (int o = 16; o >= 1; o >>= 1)
            m_ = fmaxf(m_, __shfl_xor_sync(0xffffffffu, m_, o));
        if (lane == 0) red[wid] = m_;
        __syncthreads();
        if (tid == 0) {
            float mm = red[0];
            for (int w = 1; w < 8; w++) mm = fmaxf(mm, red[w]);
            red[8] = mm;
        }
        __syncthreads();
        const float bm = red[8];
        const float e = (tid < TT) ? __expf(x - bm) : 0.f;
        if (tid < TT) wS[tid] = e;
        float s_ = e;
#pragma unroll
        for (int o = 16; o >= 1; o >>= 1)
            s_ += __shfl_xor_sync(0xffffffffu, s_, o);
        if (lane == 0) red[wid] = s_;
        __syncthreads();
        if (tid == 0) {
            float ss = 0.f;
            for (int w = 0; w < 8; w++) ss += red[w];
            red[8] = ss;
        }
        __syncthreads();
        const float inv = 1.0f / red[8];

        // attn row: sum_kb w[kb] * q[i][kb][d]
        if (tid < HD) {
            const float* qi = g_q + i * TT * HD + tid;
            float a0 = 0.f, a1 = 0.f, a2 = 0.f, a3 = 0.f;
#pragma unroll 4
            for (int kb = 0; kb < TT; kb += 4) {
                a0 = fmaf(wS[kb + 0], qi[(kb + 0) * HD], a0);
                a1 = fmaf(wS[kb + 1], qi[(kb + 1) * HD], a1);
                a2 = fmaf(wS[kb + 2], qi[(kb + 2) * HD], a2);
                a3 = fmaf(wS[kb + 3], qi[(kb + 3) * HD], a3);
            }
            g_attn[(aq * BB + b) * DD + h * HD + tid] = ((a0 + a1) + (a2 + a3)) * inv;
        }
        __syncthreads();
    }
}

// =================================================================
// Kernel 3: out projection (unchanged).
// =================================================================
__global__ __launch_bounds__(256) void outproj_kernel(
    const float* __restrict__ Wo, const float* __restrict__ bo,
    float* __restrict__ out)
{
    __shared__ float As[16 * 68];
    __shared__ float Bs[16 * 68];

    const int m0 = blockIdx.y * 64;
    const int n0 = blockIdx.x * 64;
    const int tid = threadIdx.x;
    const int tm0 = (tid >> 4) << 2;
    const int tn0 = (tid & 15) << 2;

    u64 acc2[4][2];
#pragma unroll
    for (int r = 0; r < 4; r++)
#pragma unroll
        for (int c = 0; c < 2; c++) acc2[r][c] = 0ull;

    for (int k0 = 0; k0 < DD; k0 += 16) {
        for (int idx = tid; idx < 1024; idx += 256) {
            const int row = idx >> 4, kk = idx & 15;
            As[kk * 68 + row] = g_attn[(m0 + row) * DD + k0 + kk];
            Bs[kk * 68 + row] = Wo[(n0 + row) * DD + k0 + kk];
        }
        __syncthreads();
#pragma unroll
        for (int kk = 0; kk < 16; kk++) {
            const float4 av = *(const float4*)(As + kk * 68 + tm0);
            const ulonglong2 bv = *(const ulonglong2*)(Bs + kk * 68 + tn0);
            const u64 b2[2] = {bv.x, bv.y};
            const u64 ap[4] = {pack_dup(av.x), pack_dup(av.y),
                               pack_dup(av.z), pack_dup(av.w)};
#pragma unroll
            for (int r = 0; r < 4; r++)
#pragma unroll
                for (int c = 0; c < 2; c++)
                    ffma2(acc2[r][c], ap[r], b2[c]);
        }
        __syncthreads();
    }

#pragma unroll
    for (int r = 0; r < 4; r++) {
        float accr[4];
        unpack2(acc2[r][0], accr[0], accr[1]);
        unpack2(acc2[r][1], accr[2], accr[3]);
#pragma unroll
        for (int c = 0; c < 4; c++) {
            const int m = m0 + tm0 + r;
            const int n = n0 + tn0 + c;
            out[m * DD + n] = accr[c] + bo[n];
        }
    }
}

// =================================================================
extern "C" void kernel_launch(void* const* d_in, const int* in_sizes, int n_in,
                              void* d_out, int out_size)
{
    (void)in_sizes; (void)n_in; (void)out_size;
    const float* q   = (const float*)d_in[0];
    const float* k   = (const float*)d_in[1];
    const float* v   = (const float*)d_in[2];
    const float* cb  = (const float*)d_in[3];
    const float* ipw = (const float*)d_in[4];
    const float* ipb = (const float*)d_in[5];
    const float* ow  = (const float*)d_in[6];
    const float* ob  = (const float*)d_in[7];
    float* out = (float*)d_out;

    cudaFuncSetAttribute(cube_kernel,
                         cudaFuncAttributeMaxDynamicSharedMemorySize, SM_BYTES);

    proj_kernel<<<dim3(8, 16, 3), 256>>>(q, k, v, ipw, ipb);
    cube_kernel<<<dim3(128, 8), 256, SM_BYTES>>>(cb);
    outproj_kernel<<<dim3(8, 16), 256>>>(ow, ob, out);
}

// round 14
// speedup vs baseline: 1.5650x; 1.1972x over previous
#include <cuda_runtime.h>
#include <cuda_bf16.h>
#include <math_constants.h>
#include <cstdint>

// Problem constants
#define TT   128          // sequence length
#define BB   8            // batch
#define DD   512          // embed dim
#define HH   8            // heads
#define HD   64           // head dim
#define II   64           // B*H
#define SCALING 0.125f    // 64^-0.5

typedef unsigned long long u64;

// ---------------- packed f32x2 helpers (proj kernels) ----------------
__device__ __forceinline__ u64 pack_dup(float w) {
    u64 p; unsigned int wu = __float_as_uint(w);
    asm("mov.b64 %0, {%1, %1};" : "=l"(p) : "r"(wu));
    return p;
}
__device__ __forceinline__ void ffma2(u64& d, u64 a, u64 b) {
    asm("fma.rn.f32x2 %0, %1, %2, %0;" : "+l"(d) : "l"(a), "l"(b));
}
__device__ __forceinline__ void unpack2(u64 p, float& lo, float& hi) {
    unsigned int l, h;
    asm("mov.b64 {%0, %1}, %2;" : "=r"(l), "=r"(h) : "l"(p));
    lo = __uint_as_float(l); hi = __uint_as_float(h);
}

// ---------------- warp-MMA helpers ----------------
__device__ __forceinline__ uint32_t smem_u32(const void* p) {
    uint32_t a;
    asm("{ .reg .u64 t; cvta.to.shared.u64 t, %1; cvt.u32.u64 %0, t; }" : "=r"(a) : "l"(p));
    return a;
}
__device__ __forceinline__ void ldsm_x4(uint32_t a[4], uint32_t addr) {
    asm volatile("ldmatrix.sync.aligned.m8n8.x4.shared.b16 {%0,%1,%2,%3}, [%4];"
        : "=r"(a[0]), "=r"(a[1]), "=r"(a[2]), "=r"(a[3]) : "r"(addr));
}
__device__ __forceinline__ void mma16816(float d[4], const uint32_t a[4], const uint32_t b0, const uint32_t b1) {
    asm volatile("mma.sync.aligned.m16n8k16.row.col.f32.bf16.bf16.f32 "
        "{%0,%1,%2,%3}, {%4,%5,%6,%7}, {%8,%9}, {%0,%1,%2,%3};"
        : "+f"(d[0]), "+f"(d[1]), "+f"(d[2]), "+f"(d[3])
        : "r"(a[0]), "r"(a[1]), "r"(a[2]), "r"(a[3]), "r"(b0), "r"(b1));
}
#define SWZ(o) ((o) ^ ((((uint32_t)(o)) >> 3) & 0x70))

__device__ __forceinline__ uint32_t pack_bf2(float lo, float hi) {
    __nv_bfloat162 h2 = __floats2bfloat162_rn(lo, hi);
    return *(uint32_t*)&h2;
}

// ---------------- scratch (no allocations allowed) ----------------
__device__ float g_q[II * TT * HD];       // [i][t][hd], scaled
__device__ float g_k[II * TT * HD];
__device__ float g_attn[TT * BB * DD];    // row m = a*8+b, col = h*64+d
// pre-swizzled per-head V split tiles: [i][16KB], layout row=c (0..127), col=t (0..63) bf16, SW128
__device__ __nv_bfloat16 g_vhi[II * 8192];
__device__ __nv_bfloat16 g_vlo[II * 8192];

// =================================================================
// Kernel 1: packed in-projection. For z==2 (V) the epilogue writes
// split-bf16 pre-swizzled tiles instead of f32.
// =================================================================
__global__ __launch_bounds__(256) void proj_kernel(
    const float* __restrict__ qin, const float* __restrict__ kin,
    const float* __restrict__ vin, const float* __restrict__ W,
    const float* __restrict__ bias)
{
    __shared__ float As[16 * 68];
    __shared__ float Bs[16 * 68];

    const int z = blockIdx.z;
    const float* A  = (z == 0) ? qin : ((z == 1) ? kin : vin);
    const float* Wz = W + z * DD * DD;
    const float* bz = bias + z * DD;

    const int m0 = blockIdx.y * 64;
    const int n0 = blockIdx.x * 64;
    const int tid = threadIdx.x;
    const int tm0 = (tid >> 4) << 2;
    const int tn0 = (tid & 15) << 2;

    u64 acc2[4][2];
#pragma unroll
    for (int r = 0; r < 4; r++)
#pragma unroll
        for (int c = 0; c < 2; c++) acc2[r][c] = 0ull;

    for (int k0 = 0; k0 < DD; k0 += 16) {
        for (int idx = tid; idx < 1024; idx += 256) {
            const int row = idx >> 4, kk = idx & 15;
            As[kk * 68 + row] = A[(m0 + row) * DD + k0 + kk];
            Bs[kk * 68 + row] = Wz[(n0 + row) * DD + k0 + kk];
        }
        __syncthreads();
#pragma unroll
        for (int kk = 0; kk < 16; kk++) {
            const float4 av = *(const float4*)(As + kk * 68 + tm0);
            const ulonglong2 bv = *(const ulonglong2*)(Bs + kk * 68 + tn0);
            const u64 b2[2] = {bv.x, bv.y};
            const u64 ap[4] = {pack_dup(av.x), pack_dup(av.y),
                               pack_dup(av.z), pack_dup(av.w)};
#pragma unroll
            for (int r = 0; r < 4; r++)
#pragma unroll
                for (int c = 0; c < 2; c++)
                    ffma2(acc2[r][c], ap[r], b2[c]);
        }
        __syncthreads();
    }

    const float scale = (z == 0) ? SCALING : 1.0f;
#pragma unroll
    for (int r = 0; r < 4; r++) {
        float accr[4];
        unpack2(acc2[r][0], accr[0], accr[1]);
        unpack2(acc2[r][1], accr[2], accr[3]);
#pragma unroll
        for (int c = 0; c < 4; c++) {
            const int m = m0 + tm0 + r;          // = a*8 + b
            const int n = n0 + tn0 + c;          // = h*64 + t
            const float val = (accr[c] + bz[n]) * scale;
            const int a_ = m >> 3, b_ = m & 7;
            const int h_ = n >> 6, t_ = n & 63;
            const int i_ = b_ * HH + h_;
            if (z == 2) {
                // split-bf16 V, pre-swizzled tile layout [i][row=a_][t]
                const __nv_bfloat16 vh = __float2bfloat16(val);
                const __nv_bfloat16 vl = __float2bfloat16(val - __bfloat162float(vh));
                const uint32_t off = SWZ((uint32_t)(a_ * 128 + t_ * 2));  // byte offset
                *(__nv_bfloat16*)((char*)(g_vhi + i_ * 8192) + off) = vh;
                *(__nv_bfloat16*)((char*)(g_vlo + i_ * 8192) + off) = vl;
            } else {
                float* dst = (z == 0) ? g_q : g_k;
                dst[(i_ * TT + a_) * HD + t_] = val;
            }
        }
    }
}

// =================================================================
// Kernel 2: cube via warp MMA. grid (128, 8) = (aq, b), 512 threads.
// Warp w = (wr = w&7, wc = w>>3): rows [wr*16, wr*16+16), cols [wc*64, wc*64+64).
// A = K ⊙ q_a (split-bf16, built per head); B = V (split-bf16, precomputed).
// =================================================================
#define OFF_KHI  0
#define OFF_KLO  16384
#define OFF_VHI  32768
#define OFF_VLO  49152
#define OFF_FLT  65536
#define FI_BIAS  0                    // 128*129
#define FI_QA    16512                // 64
#define FI_FUSED (16512 + 64)         // 128
#define FI_W     (FI_FUSED + 128)     // 128
#define FI_RED   (FI_W + 128)         // 16
#define FI_PART  (FI_RED + 16)        // 512
#define SM_FLOATS (FI_PART + 512)
#define SM_BYTES  (OFF_FLT + SM_FLOATS * 4)

__global__ __launch_bounds__(512) void cube_kernel(const float* __restrict__ bias_g)
{
    extern __shared__ char smem[];
    float* fs     = (float*)(smem + OFF_FLT);
    float* biasS  = fs + FI_BIAS;
    float* qaS    = fs + FI_QA;
    float* fusedS = fs + FI_FUSED;
    float* wS     = fs + FI_W;
    float* red    = fs + FI_RED;
    float* partS  = fs + FI_PART;

    const uint32_t sbase = smem_u32(smem);

    const int aq = blockIdx.x, b = blockIdx.y;
    const int tid  = threadIdx.x;
    const int lane = tid & 31, wid = tid >> 5;
    const int g    = lane >> 2, tig = lane & 3;
    const int wr   = wid & 7, wc = wid >> 3;
    const int m0   = wr * 16;
    const int cbase = wc * 64;

    // bias tile for (b, aq): [kb][c], padded stride 129
    const float* bsrc = bias_g + ((size_t)(b * TT + aq) * TT) * TT;
    for (int idx = tid; idx < TT * TT; idx += 512) {
        const int kb = idx >> 7, c = idx & 127;
        biasS[kb * 129 + c] = bsrc[idx];
    }

    // head-invariant per-lane ldmatrix address bases (byte offsets, pre-swizzle)
    const uint32_t abase = (uint32_t)((m0 + (lane & 15)) * 128 + ((lane >> 4) << 4));
    const uint32_t bbase = (uint32_t)((cbase + (lane & 7) + ((lane >> 4) << 3)) * 128
                                      + (((lane >> 3) & 1) << 4));

    for (int h = 0; h < HH; ++h) {
        const int i = b * HH + h;

        if (tid < 64) qaS[tid] = g_q[(i * TT + aq) * HD + tid];
        __syncthreads();

        // copy precomputed V split tiles (16KB each), swizzle preserved
        {
            const float4* vh = (const float4*)(g_vhi + i * 8192);
            const float4* vl = (const float4*)(g_vlo + i * 8192);
            float4* dh = (float4*)(smem + OFF_VHI);
            float4* dl = (float4*)(smem + OFF_VLO);
#pragma unroll
            for (int j = tid; j < 1024; j += 512) { dh[j] = vh[j]; dl[j] = vl[j]; }
        }
        // build A = K ⊙ q_a split-bf16 tiles (vectorized float4 -> STS.64)
        for (int idx = tid; idx < 2048; idx += 512) {
            const int r = idx >> 4, tq = idx & 15;
            const float4 kf = *(const float4*)(g_k + (i * TT + r) * HD + tq * 4);
            const float4 qa = *(const float4*)(qaS + tq * 4);
            const float p0 = kf.x * qa.x, p1 = kf.y * qa.y;
            const float p2 = kf.z * qa.z, p3 = kf.w * qa.w;
            const __nv_bfloat16 h0 = __float2bfloat16(p0), h1 = __float2bfloat16(p1);
            const __nv_bfloat16 h2 = __float2bfloat16(p2), h3 = __float2bfloat16(p3);
            uint2 hi, lo;
            hi.x = pack_bf2(p0, p1); hi.y = pack_bf2(p2, p3);
            lo.x = pack_bf2(p0 - __bfloat162float(h0), p1 - __bfloat162float(h1));
            lo.y = pack_bf2(p2 - __bfloat162float(h2), p3 - __bfloat162float(h3));
            const uint32_t off = SWZ((uint32_t)(r * 128 + tq * 8));
            *(uint2*)(smem + OFF_KHI + off) = hi;
            *(uint2*)(smem + OFF_KLO + off) = lo;
        }
        __syncthreads();

        // S strip [16 x 64] in registers: acc[nt][4], nt = local 8-col tile
        float acc[8][4];
#pragma unroll
        for (int nt = 0; nt < 8; nt++)
#pragma unroll
            for (int j = 0; j < 4; j++) acc[nt][j] = 0.f;

#pragma unroll
        for (int kc = 0; kc < 4; kc++) {
            uint32_t ah[4], al[4];
            const uint32_t ao = SWZ(abase + kc * 32);
            ldsm_x4(ah, sbase + OFF_KHI + ao);
            ldsm_x4(al, sbase + OFF_KLO + ao);
#pragma unroll
            for (int p = 0; p < 4; p++) {
                const uint32_t bo = SWZ(bbase + p * 2048 + kc * 32);
                uint32_t bh[4], bl[4];
                ldsm_x4(bh, sbase + OFF_VHI + bo);
                ldsm_x4(bl, sbase + OFF_VLO + bo);
                mma16816(acc[2 * p],     ah, bh[0], bh[1]);
                mma16816(acc[2 * p + 1], ah, bh[2], bh[3]);
                mma16816(acc[2 * p],     al, bh[0], bh[1]);
                mma16816(acc[2 * p + 1], al, bh[2], bh[3]);
                mma16816(acc[2 * p],     ah, bl[0], bl[1]);
                mma16816(acc[2 * p + 1], ah, bl[2], bl[3]);
            }
        }

        // epilogue: bias add + partial mean/max over this warp's 64 cols
        {
            const int r0 = m0 + g, r1 = r0 + 8;
            float s0 = 0.f, s1 = 0.f;
            float mx0 = -CUDART_INF_F, mx1 = -CUDART_INF_F;
            const float* b0 = biasS + r0 * 129 + cbase + tig * 2;
            const float* b1 = biasS + r1 * 129 + cbase + tig * 2;
#pragma unroll
            for (int nt = 0; nt < 8; nt++) {
                const float v00 = acc[nt][0] + b0[nt * 8];
                const float v01 = acc[nt][1] + b0[nt * 8 + 1];
                const float v10 = acc[nt][2] + b1[nt * 8];
                const float v11 = acc[nt][3] + b1[nt * 8 + 1];
                s0 += v00 + v01;  mx0 = fmaxf(mx0, fmaxf(v00, v01));
                s1 += v10 + v11;  mx1 = fmaxf(mx1, fmaxf(v10, v11));
            }
#pragma unroll
            for (int o = 1; o <= 2; o <<= 1) {
                s0  += __shfl_xor_sync(0xffffffffu, s0, o);
                s1  += __shfl_xor_sync(0xffffffffu, s1, o);
                mx0 = fmaxf(mx0, __shfl_xor_sync(0xffffffffu, mx0, o));
                mx1 = fmaxf(mx1, __shfl_xor_sync(0xffffffffu, mx1, o));
            }
            if (tig == 0) {
                partS[wc * 128 + r0]       = s0;
                partS[wc * 128 + r1]       = s1;
                partS[256 + wc * 128 + r0] = mx0;
                partS[256 + wc * 128 + r1] = mx1;
            }
        }
        __syncthreads();

        // fused value + softmax over kb (first 128 threads)
        float x = -CUDART_INF_F;
        if (tid < TT) {
            const float sum2 = partS[tid] + partS[128 + tid];
            const float mx2  = fmaxf(partS[256 + tid], partS[384 + tid]);
            x = sum2 * (1.0f / 128.0f) + mx2;
        }
        float m_ = x;
#pragma unroll
        for (int o = 16; o >= 1; o >>= 1)
            m_ = fmaxf(m_, __shfl_xor_sync(0xffffffffu, m_, o));
        if (lane == 0 && wid < 4) red[wid] = m_;
        __syncthreads();
        if (tid == 0) {
            float mm = red[0];
            for (int w = 1; w < 4; w++) mm = fmaxf(mm, red[w]);
            red[8] = mm;
        }
        __syncthreads();
        const float bm = red[8];
        const float e = (tid < TT) ? __expf(x - bm) : 0.f;
        if (tid < TT) wS[tid] = e;
        float s_ = e;
#pragma unroll
        for (int o = 16; o >= 1; o >>= 1)
            s_ += __shfl_xor_sync(0xffffffffu, s_, o);
        if (lane == 0 && wid < 4) red[wid] = s_;
        __syncthreads();
        if (tid == 0) {
            float ss = 0.f;
            for (int w = 0; w < 4; w++) ss += red[w];
            red[8] = ss;
        }
        __syncthreads();
        const float inv = 1.0f / red[8];

        // attn row: sum_kb w[kb] * q[i][kb][d]
        if (tid < HD) {
            const float* qi = g_q + i * TT * HD + tid;
            float a0 = 0.f, a1 = 0.f, a2 = 0.f, a3 = 0.f;
#pragma unroll 4
            for (int kb = 0; kb < TT; kb += 4) {
                a0 = fmaf(wS[kb + 0], qi[(kb + 0) * HD], a0);
                a1 = fmaf(wS[kb + 1], qi[(kb + 1) * HD], a1);
                a2 = fmaf(wS[kb + 2], qi[(kb + 2) * HD], a2);
                a3 = fmaf(wS[kb + 3], qi[(kb + 3) * HD], a3);
            }
            g_attn[(aq * BB + b) * DD + h * HD + tid] = ((a0 + a1) + (a2 + a3)) * inv;
        }
        __syncthreads();
    }
}

// =================================================================
// Kernel 3: out projection (unchanged).
// =================================================================
__global__ __launch_bounds__(256) void outproj_kernel(
    const float* __restrict__ Wo, const float* __restrict__ bo,
    float* __restrict__ out)
{
    __shared__ float As[16 * 68];
    __shared__ float Bs[16 * 68];

    const int m0 = blockIdx.y * 64;
    const int n0 = blockIdx.x * 64;
    const int tid = threadIdx.x;
    const int tm0 = (tid >> 4) << 2;
    const int tn0 = (tid & 15) << 2;

    u64 acc2[4][2];
#pragma unroll
    for (int r = 0; r < 4; r++)
#pragma unroll
        for (int c = 0; c < 2; c++) acc2[r][c] = 0ull;

    for (int k0 = 0; k0 < DD; k0 += 16) {
        for (int idx = tid; idx < 1024; idx += 256) {
            const int row = idx >> 4, kk = idx & 15;
            As[kk * 68 + row] = g_attn[(m0 + row) * DD + k0 + kk];
            Bs[kk * 68 + row] = Wo[(n0 + row) * DD + k0 + kk];
        }
        __syncthreads();
#pragma unroll
        for (int kk = 0; kk < 16; kk++) {
            const float4 av = *(const float4*)(As + kk * 68 + tm0);
            const ulonglong2 bv = *(const ulonglong2*)(Bs + kk * 68 + tn0);
            const u64 b2[2] = {bv.x, bv.y};
            const u64 ap[4] = {pack_dup(av.x), pack_dup(av.y),
                               pack_dup(av.z), pack_dup(av.w)};
#pragma unroll
            for (int r = 0; r < 4; r++)
#pragma unroll
                for (int c = 0; c < 2; c++)
                    ffma2(acc2[r][c], ap[r], b2[c]);
        }
        __syncthreads();
    }

#pragma unroll
    for (int r = 0; r < 4; r++) {
        float accr[4];
        unpack2(acc2[r][0], accr[0], accr[1]);
        unpack2(acc2[r][1], accr[2], accr[3]);
#pragma unroll
        for (int c = 0; c < 4; c++) {
            const int m = m0 + tm0 + r;
            const int n = n0 + tn0 + c;
            out[m * DD + n] = accr[c] + bo[n];
        }
    }
}

// =================================================================
extern "C" void kernel_launch(void* const* d_in, const int* in_sizes, int n_in,
                              void* d_out, int out_size)
{
    (void)in_sizes; (void)n_in; (void)out_size;
    const float* q   = (const float*)d_in[0];
    const float* k   = (const float*)d_in[1];
    const float* v   = (const float*)d_in[2];
    const float* cb  = (const float*)d_in[3];
    const float* ipw = (const float*)d_in[4];
    const float* ipb = (const float*)d_in[5];
    const float* ow  = (const float*)d_in[6];
    const float* ob  = (const float*)d_in[7];
    float* out = (float*)d_out;

    cudaFuncSetAttribute(cube_kernel,
                         cudaFuncAttributeMaxDynamicSharedMemorySize, SM_BYTES);

    proj_kernel<<<dim3(8, 16, 3), 256>>>(q, k, v, ipw, ipb);
    cube_kernel<<<dim3(128, 8), 512, SM_BYTES>>>(cb);
    outproj_kernel<<<dim3(8, 16), 256>>>(ow, ob, out);
}

// round 15
// speedup vs baseline: 1.9976x; 1.2764x over previous
#include <cuda_runtime.h>
#include <cuda_bf16.h>
#include <math_constants.h>
#include <cstdint>

// Problem constants
#define TT   128          // sequence length
#define BB   8            // batch
#define DD   512          // embed dim
#define HH   8            // heads
#define HD   64           // head dim
#define II   64           // B*H
#define SCALING 0.125f    // 64^-0.5

typedef unsigned long long u64;

// ---------------- packed f32x2 helpers (proj kernels) ----------------
__device__ __forceinline__ u64 pack_dup(float w) {
    u64 p; unsigned int wu = __float_as_uint(w);
    asm("mov.b64 %0, {%1, %1};" : "=l"(p) : "r"(wu));
    return p;
}
__device__ __forceinline__ void ffma2(u64& d, u64 a, u64 b) {
    asm("fma.rn.f32x2 %0, %1, %2, %0;" : "+l"(d) : "l"(a), "l"(b));
}
__device__ __forceinline__ void unpack2(u64 p, float& lo, float& hi) {
    unsigned int l, h;
    asm("mov.b64 {%0, %1}, %2;" : "=r"(l), "=r"(h) : "l"(p));
    lo = __uint_as_float(l); hi = __uint_as_float(h);
}

// ---------------- warp-MMA helpers ----------------
__device__ __forceinline__ uint32_t smem_u32(const void* p) {
    uint32_t a;
    asm("{ .reg .u64 t; cvta.to.shared.u64 t, %1; cvt.u32.u64 %0, t; }" : "=r"(a) : "l"(p));
    return a;
}
__device__ __forceinline__ void ldsm_x4(uint32_t a[4], uint32_t addr) {
    asm volatile("ldmatrix.sync.aligned.m8n8.x4.shared.b16 {%0,%1,%2,%3}, [%4];"
        : "=r"(a[0]), "=r"(a[1]), "=r"(a[2]), "=r"(a[3]) : "r"(addr));
}
__device__ __forceinline__ void mma16816(float d[4], const uint32_t a[4], const uint32_t b0, const uint32_t b1) {
    asm volatile("mma.sync.aligned.m16n8k16.row.col.f32.bf16.bf16.f32 "
        "{%0,%1,%2,%3}, {%4,%5,%6,%7}, {%8,%9}, {%0,%1,%2,%3};"
        : "+f"(d[0]), "+f"(d[1]), "+f"(d[2]), "+f"(d[3])
        : "r"(a[0]), "r"(a[1]), "r"(a[2]), "r"(a[3]), "r"(b0), "r"(b1));
}
#define SWZ(o) ((o) ^ ((((uint32_t)(o)) >> 3) & 0x70))

__device__ __forceinline__ uint32_t pack_bf2(float lo, float hi) {
    __nv_bfloat162 h2 = __floats2bfloat162_rn(lo, hi);
    return *(uint32_t*)&h2;
}

// ---------------- scratch (no allocations allowed) ----------------
__device__ float g_q[II * TT * HD];       // [i][t][hd], scaled
__device__ float g_k[II * TT * HD];
__device__ float g_attn[TT * BB * DD];    // row m = a*8+b, col = h*64+d
// pre-swizzled per-head V split tiles: [i][16KB], row=c (0..127), col=t (0..63) bf16, SW128
__device__ __nv_bfloat16 g_vhi[II * 8192];
__device__ __nv_bfloat16 g_vlo[II * 8192];

// =================================================================
// Kernel 1: packed in-projection. For z==2 (V) the epilogue writes
// split-bf16 pre-swizzled tiles instead of f32.  (unchanged)
// =================================================================
__global__ __launch_bounds__(256) void proj_kernel(
    const float* __restrict__ qin, const float* __restrict__ kin,
    const float* __restrict__ vin, const float* __restrict__ W,
    const float* __restrict__ bias)
{
    __shared__ float As[16 * 68];
    __shared__ float Bs[16 * 68];

    const int z = blockIdx.z;
    const float* A  = (z == 0) ? qin : ((z == 1) ? kin : vin);
    const float* Wz = W + z * DD * DD;
    const float* bz = bias + z * DD;

    const int m0 = blockIdx.y * 64;
    const int n0 = blockIdx.x * 64;
    const int tid = threadIdx.x;
    const int tm0 = (tid >> 4) << 2;
    const int tn0 = (tid & 15) << 2;

    u64 acc2[4][2];
#pragma unroll
    for (int r = 0; r < 4; r++)
#pragma unroll
        for (int c = 0; c < 2; c++) acc2[r][c] = 0ull;

    for (int k0 = 0; k0 < DD; k0 += 16) {
        for (int idx = tid; idx < 1024; idx += 256) {
            const int row = idx >> 4, kk = idx & 15;
            As[kk * 68 + row] = A[(m0 + row) * DD + k0 + kk];
            Bs[kk * 68 + row] = Wz[(n0 + row) * DD + k0 + kk];
        }
        __syncthreads();
#pragma unroll
        for (int kk = 0; kk < 16; kk++) {
            const float4 av = *(const float4*)(As + kk * 68 + tm0);
            const ulonglong2 bv = *(const ulonglong2*)(Bs + kk * 68 + tn0);
            const u64 b2[2] = {bv.x, bv.y};
            const u64 ap[4] = {pack_dup(av.x), pack_dup(av.y),
                               pack_dup(av.z), pack_dup(av.w)};
#pragma unroll
            for (int r = 0; r < 4; r++)
#pragma unroll
                for (int c = 0; c < 2; c++)
                    ffma2(acc2[r][c], ap[r], b2[c]);
        }
        __syncthreads();
    }

    const float scale = (z == 0) ? SCALING : 1.0f;
#pragma unroll
    for (int r = 0; r < 4; r++) {
        float accr[4];
        unpack2(acc2[r][0], accr[0], accr[1]);
        unpack2(acc2[r][1], accr[2], accr[3]);
#pragma unroll
        for (int c = 0; c < 4; c++) {
            const int m = m0 + tm0 + r;          // = a*8 + b
            const int n = n0 + tn0 + c;          // = h*64 + t
            const float val = (accr[c] + bz[n]) * scale;
            const int a_ = m >> 3, b_ = m & 7;
            const int h_ = n >> 6, t_ = n & 63;
            const int i_ = b_ * HH + h_;
            if (z == 2) {
                const __nv_bfloat16 vh = __float2bfloat16(val);
                const __nv_bfloat16 vl = __float2bfloat16(val - __bfloat162float(vh));
                const uint32_t off = SWZ((uint32_t)(a_ * 128 + t_ * 2));  // byte offset
                *(__nv_bfloat16*)((char*)(g_vhi + i_ * 8192) + off) = vh;
                *(__nv_bfloat16*)((char*)(g_vlo + i_ * 8192) + off) = vl;
            } else {
                float* dst = (z == 0) ? g_q : g_k;
                dst[(i_ * TT + a_) * HD + t_] = val;
            }
        }
    }
}

// =================================================================
// Kernel 2: cube via warp MMA, ONE HEAD PER CTA.
// grid (128, 8, 8) = (aq, b, h), 512 threads, 2 CTAs/SM.
// Warp w = (wr = w&7, wc = w>>3): rows [wr*16,+16), cols [wc*64,+64).
// Bias is read directly from global (L2) in the epilogue — used once.
// =================================================================
#define OFF_KHI  0
#define OFF_KLO  16384
#define OFF_VHI  32768
#define OFF_VLO  49152
#define OFF_FLT  65536
#define FI_QA    0                    // 64
#define FI_W     64                   // 128 (softmax weights)
#define FI_RED   (FI_W + 128)         // 16
#define FI_PART  (FI_RED + 16)        // 512: [sum h0 | sum h1 | max h0 | max h1]
#define FI_APART (FI_PART + 512)      // 512: attn partials [grp][d]
#define SM_FLOATS (FI_APART + 512)
#define SM_BYTES  (OFF_FLT + SM_FLOATS * 4)

__global__ __launch_bounds__(512, 2) void cube_kernel(const float* __restrict__ bias_g)
{
    extern __shared__ char smem[];
    float* fs     = (float*)(smem + OFF_FLT);
    float* qaS    = fs + FI_QA;
    float* wS     = fs + FI_W;
    float* red    = fs + FI_RED;
    float* partS  = fs + FI_PART;
    float* apartS = fs + FI_APART;

    const uint32_t sbase = smem_u32(smem);

    const int aq = blockIdx.x, b = blockIdx.y, h = blockIdx.z;
    const int i = b * HH + h;
    const int tid  = threadIdx.x;
    const int lane = tid & 31, wid = tid >> 5;
    const int g    = lane >> 2, tig = lane & 3;
    const int wr   = wid & 7, wc = wid >> 3;
    const int m0   = wr * 16;
    const int cbase = wc * 64;

    // head-invariant per-lane ldmatrix address bases (byte offsets, pre-swizzle)
    const uint32_t abase = (uint32_t)((m0 + (lane & 15)) * 128 + ((lane >> 4) << 4));
    const uint32_t bbase = (uint32_t)((cbase + (lane & 7) + ((lane >> 4) << 3)) * 128
                                      + (((lane >> 3) & 1) << 4));

    if (tid < 64) qaS[tid] = g_q[(i * TT + aq) * HD + tid];
    __syncthreads();

    // copy precomputed V split tiles (16KB each), swizzle preserved
    {
        const float4* vh = (const float4*)(g_vhi + i * 8192);
        const float4* vl = (const float4*)(g_vlo + i * 8192);
        float4* dh = (float4*)(smem + OFF_VHI);
        float4* dl = (float4*)(smem + OFF_VLO);
#pragma unroll
        for (int j = tid; j < 1024; j += 512) { dh[j] = vh[j]; dl[j] = vl[j]; }
    }
    // build A = K ⊙ q_a split-bf16 tiles (vectorized float4 -> STS.64)
    for (int idx = tid; idx < 2048; idx += 512) {
        const int r = idx >> 4, tq = idx & 15;
        const float4 kf = *(const float4*)(g_k + (i * TT + r) * HD + tq * 4);
        const float4 qa = *(const float4*)(qaS + tq * 4);
        const float p0 = kf.x * qa.x, p1 = kf.y * qa.y;
        const float p2 = kf.z * qa.z, p3 = kf.w * qa.w;
        const __nv_bfloat16 h0 = __float2bfloat16(p0), h1 = __float2bfloat16(p1);
        const __nv_bfloat16 h2 = __float2bfloat16(p2), h3 = __float2bfloat16(p3);
        uint2 hi, lo;
        hi.x = pack_bf2(p0, p1); hi.y = pack_bf2(p2, p3);
        lo.x = pack_bf2(p0 - __bfloat162float(h0), p1 - __bfloat162float(h1));
        lo.y = pack_bf2(p2 - __bfloat162float(h2), p3 - __bfloat162float(h3));
        const uint32_t off = SWZ((uint32_t)(r * 128 + tq * 8));
        *(uint2*)(smem + OFF_KHI + off) = hi;
        *(uint2*)(smem + OFF_KLO + off) = lo;
    }
    __syncthreads();

    // S strip [16 x 64] in registers: acc[nt][4], nt = local 8-col tile
    float acc[8][4];
#pragma unroll
    for (int nt = 0; nt < 8; nt++)
#pragma unroll
        for (int j = 0; j < 4; j++) acc[nt][j] = 0.f;

#pragma unroll
    for (int kc = 0; kc < 4; kc++) {
        uint32_t ah[4], al[4];
        const uint32_t ao = SWZ(abase + kc * 32);
        ldsm_x4(ah, sbase + OFF_KHI + ao);
        ldsm_x4(al, sbase + OFF_KLO + ao);
#pragma unroll
        for (int p = 0; p < 4; p++) {
            const uint32_t bo = SWZ(bbase + p * 2048 + kc * 32);
            uint32_t bh[4], bl[4];
            ldsm_x4(bh, sbase + OFF_VHI + bo);
            ldsm_x4(bl, sbase + OFF_VLO + bo);
            mma16816(acc[2 * p],     ah, bh[0], bh[1]);
            mma16816(acc[2 * p + 1], ah, bh[2], bh[3]);
            mma16816(acc[2 * p],     al, bh[0], bh[1]);
            mma16816(acc[2 * p + 1], al, bh[2], bh[3]);
            mma16816(acc[2 * p],     ah, bl[0], bl[1]);
            mma16816(acc[2 * p + 1], ah, bl[2], bl[3]);
        }
    }

    // epilogue: bias (direct from global/L2, each element read once)
    // + partial mean/max over this warp's 64 cols
    {
        const int r0 = m0 + g, r1 = r0 + 8;
        const float* bsrc = bias_g + ((size_t)(b * TT + aq) * TT) * TT;
        const float* b0 = bsrc + r0 * TT + cbase + tig * 2;
        const float* b1 = bsrc + r1 * TT + cbase + tig * 2;
        float s0 = 0.f, s1 = 0.f;
        float mx0 = -CUDART_INF_F, mx1 = -CUDART_INF_F;
#pragma unroll
        for (int nt = 0; nt < 8; nt++) {
            const float v00 = acc[nt][0] + __ldg(b0 + nt * 8);
            const float v01 = acc[nt][1] + __ldg(b0 + nt * 8 + 1);
            const float v10 = acc[nt][2] + __ldg(b1 + nt * 8);
            const float v11 = acc[nt][3] + __ldg(b1 + nt * 8 + 1);
            s0 += v00 + v01;  mx0 = fmaxf(mx0, fmaxf(v00, v01));
            s1 += v10 + v11;  mx1 = fmaxf(mx1, fmaxf(v10, v11));
        }
#pragma unroll
        for (int o = 1; o <= 2; o <<= 1) {
            s0  += __shfl_xor_sync(0xffffffffu, s0, o);
            s1  += __shfl_xor_sync(0xffffffffu, s1, o);
            mx0 = fmaxf(mx0, __shfl_xor_sync(0xffffffffu, mx0, o));
            mx1 = fmaxf(mx1, __shfl_xor_sync(0xffffffffu, mx1, o));
        }
        if (tig == 0) {
            partS[wc * 128 + r0]       = s0;
            partS[wc * 128 + r1]       = s1;
            partS[256 + wc * 128 + r0] = mx0;
            partS[256 + wc * 128 + r1] = mx1;
        }
    }
    __syncthreads();

    // fused value + softmax over kb (first 128 threads)
    float x = -CUDART_INF_F;
    if (tid < TT) {
        const float sum2 = partS[tid] + partS[128 + tid];
        const float mx2  = fmaxf(partS[256 + tid], partS[384 + tid]);
        x = sum2 * (1.0f / 128.0f) + mx2;
    }
    float m_ = x;
#pragma unroll
    for (int o = 16; o >= 1; o >>= 1)
        m_ = fmaxf(m_, __shfl_xor_sync(0xffffffffu, m_, o));
    if (lane == 0 && wid < 4) red[wid] = m_;
    __syncthreads();
    if (tid == 0) {
        float mm = red[0];
        for (int w = 1; w < 4; w++) mm = fmaxf(mm, red[w]);
        red[8] = mm;
    }
    __syncthreads();
    const float bm = red[8];
    const float e = (tid < TT) ? __expf(x - bm) : 0.f;
    if (tid < TT) wS[tid] = e;
    float s_ = e;
#pragma unroll
    for (int o = 16; o >= 1; o >>= 1)
        s_ += __shfl_xor_sync(0xffffffffu, s_, o);
    if (lane == 0 && wid < 4) red[wid] = s_;
    __syncthreads();
    if (tid == 0) {
        float ss = 0.f;
        for (int w = 0; w < 4; w++) ss += red[w];
        red[8] = ss;
    }
    __syncthreads();
    const float inv = 1.0f / red[8];

    // attn row, parallel across all 512 threads:
    // thread (grp = tid>>6, d = tid&63) sums 16 kb values, then 64 threads combine.
    {
        const int d = tid & 63, grp = tid >> 6;
        const float* qi = g_q + i * TT * HD + d;
        const int kb0 = grp * 16;
        float a0 = 0.f, a1 = 0.f;
#pragma unroll
        for (int kk = 0; kk < 16; kk += 2) {
            a0 = fmaf(wS[kb0 + kk],     qi[(kb0 + kk) * HD],     a0);
            a1 = fmaf(wS[kb0 + kk + 1], qi[(kb0 + kk + 1) * HD], a1);
        }
        apartS[grp * 64 + d] = a0 + a1;
    }
    __syncthreads();
    if (tid < HD) {
        float t = 0.f;
#pragma unroll
        for (int grp = 0; grp < 8; grp++) t += apartS[grp * 64 + tid];
        g_attn[(aq * BB + b) * DD + h * HD + tid] = t * inv;
    }
}

// =================================================================
// Kernel 3: out projection (unchanged).
// =================================================================
__global__ __launch_bounds__(256) void outproj_kernel(
    const float* __restrict__ Wo, const float* __restrict__ bo,
    float* __restrict__ out)
{
    __shared__ float As[16 * 68];
    __shared__ float Bs[16 * 68];

    const int m0 = blockIdx.y * 64;
    const int n0 = blockIdx.x * 64;
    const int tid = threadIdx.x;
    const int tm0 = (tid >> 4) << 2;
    const int tn0 = (tid & 15) << 2;

    u64 acc2[4][2];
#pragma unroll
    for (int r = 0; r < 4; r++)
#pragma unroll
        for (int c = 0; c < 2; c++) acc2[r][c] = 0ull;

    for (int k0 = 0; k0 < DD; k0 += 16) {
        for (int idx = tid; idx < 1024; idx += 256) {
            const int row = idx >> 4, kk = idx & 15;
            As[kk * 68 + row] = g_attn[(m0 + row) * DD + k0 + kk];
            Bs[kk * 68 + row] = Wo[(n0 + row) * DD + k0 + kk];
        }
        __syncthreads();
#pragma unroll
        for (int kk = 0; kk < 16; kk++) {
            const float4 av = *(const float4*)(As + kk * 68 + tm0);
            const ulonglong2 bv = *(const ulonglong2*)(Bs + kk * 68 + tn0);
            const u64 b2[2] = {bv.x, bv.y};
            const u64 ap[4] = {pack_dup(av.x), pack_dup(av.y),
                               pack_dup(av.z), pack_dup(av.w)};
#pragma unroll
            for (int r = 0; r < 4; r++)
#pragma unroll
                for (int c = 0; c < 2; c++)
                    ffma2(acc2[r][c], ap[r], b2[c]);
        }
        __syncthreads();
    }

#pragma unroll
    for (int r = 0; r < 4; r++) {
        float accr[4];
        unpack2(acc2[r][0], accr[0], accr[1]);
        unpack2(acc2[r][1], accr[2], accr[3]);
#pragma unroll
        for (int c = 0; c < 4; c++) {
            const int m = m0 + tm0 + r;
            const int n = n0 + tn0 + c;
            out[m * DD + n] = accr[c] + bo[n];
        }
    }
}

// =================================================================
extern "C" void kernel_launch(void* const* d_in, const int* in_sizes, int n_in,
                              void* d_out, int out_size)
{
    (void)in_sizes; (void)n_in; (void)out_size;
    const float* q   = (const float*)d_in[0];
    const float* k   = (const float*)d_in[1];
    const float* v   = (const float*)d_in[2];
    const float* cb  = (const float*)d_in[3];
    const float* ipw = (const float*)d_in[4];
    const float* ipb = (const float*)d_in[5];
    const float* ow  = (const float*)d_in[6];
    const float* ob  = (const float*)d_in[7];
    float* out = (float*)d_out;

    cudaFuncSetAttribute(cube_kernel,
                         cudaFuncAttributeMaxDynamicSharedMemorySize, SM_BYTES);

    proj_kernel<<<dim3(8, 16, 3), 256>>>(q, k, v, ipw, ipb);
    cube_kernel<<<dim3(128, 8, 8), 512, SM_BYTES>>>(cb);
    outproj_kernel<<<dim3(8, 16), 256>>>(ow, ob, out);
}